// round 4
// baseline (speedup 1.0000x reference)
#include <cuda_runtime.h>
#include <cstdint>

// Embedding gather via TMA bulk copies (sm_103a).
// x: [32768] int32 ids; emb: [50257, 512] f32; out: [32768, 512] f32.
// even ids -> id 0 (reference: jnp.where(x % 2 == 0, 0, x)).
//
// Each row is 2048 contiguous bytes. Pure data movement -> drive it with
// cp.async.bulk (UBLKCP) through an 8-stage smem ring per CTA:
//   gmem --TMA load--> smem[slot] --TMA store--> gmem
// One elected thread issues everything; mbarrier complete_tx tracks loads,
// bulk_group wait_group.read tracks store reads of smem for slot reuse.

static constexpr int ROW_BYTES    = 2048;   // 512 * 4
static constexpr int ROWS_PER_CTA = 32;
static constexpr int STAGES       = 8;
static constexpr int DIST         = 6;      // prefetch distance = STAGES - 2
static constexpr int THREADS      = 32;

__device__ __forceinline__ uint32_t smem_u32(const void* p) {
    return (uint32_t)__cvta_generic_to_shared(p);
}

__device__ __forceinline__ void mbar_init(uint32_t mbar, uint32_t count) {
    asm volatile("mbarrier.init.shared.b64 [%0], %1;" :: "r"(mbar), "r"(count) : "memory");
}

__device__ __forceinline__ void mbar_expect_tx(uint32_t mbar, uint32_t bytes) {
    asm volatile("mbarrier.arrive.expect_tx.shared.b64 _, [%0], %1;"
                 :: "r"(mbar), "r"(bytes) : "memory");
}

__device__ __forceinline__ void mbar_wait_parity(uint32_t mbar, uint32_t parity) {
    asm volatile(
        "{\n\t"
        ".reg .pred P1;\n\t"
        "WAIT_LOOP_%=:\n\t"
        "mbarrier.try_wait.parity.acquire.cta.shared::cta.b64 P1, [%0], %1, 0x989680;\n\t"
        "@P1 bra.uni WAIT_DONE_%=;\n\t"
        "bra.uni WAIT_LOOP_%=;\n\t"
        "WAIT_DONE_%=:\n\t"
        "}"
        :: "r"(mbar), "r"(parity) : "memory");
}

__device__ __forceinline__ void bulk_load(uint32_t dst_smem, const void* src_gmem,
                                          uint32_t bytes, uint32_t mbar) {
    asm volatile(
        "cp.async.bulk.shared::cta.global.mbarrier::complete_tx::bytes "
        "[%0], [%1], %2, [%3];"
        :: "r"(dst_smem), "l"(src_gmem), "r"(bytes), "r"(mbar) : "memory");
}

__device__ __forceinline__ void bulk_store(void* dst_gmem, uint32_t src_smem,
                                           uint32_t bytes) {
    asm volatile(
        "cp.async.bulk.global.shared::cta.bulk_group [%0], [%1], %2;"
        :: "l"(dst_gmem), "r"(src_smem), "r"(bytes) : "memory");
}

__device__ __forceinline__ void bulk_commit() {
    asm volatile("cp.async.bulk.commit_group;" ::: "memory");
}

template <int N>
__device__ __forceinline__ void bulk_wait_read() {
    asm volatile("cp.async.bulk.wait_group.read %0;" :: "n"(N) : "memory");
}

template <int N>
__device__ __forceinline__ void bulk_wait_all() {
    asm volatile("cp.async.bulk.wait_group %0;" :: "n"(N) : "memory");
}

__global__ __launch_bounds__(THREADS)
void embed_tma_kernel(const int* __restrict__ x,
                      const char* __restrict__ emb,
                      char* __restrict__ out,
                      int n_rows) {
    __shared__ alignas(128) char buf[STAGES][ROW_BYTES];
    __shared__ alignas(8) unsigned long long mbar[STAGES];
    __shared__ int toks[ROWS_PER_CTA];

    const int base = blockIdx.x * ROWS_PER_CTA;
    const int tid  = threadIdx.x;

    // Load + remap the 32 token ids for this CTA (one per thread).
    {
        int r = base + tid;
        int tok = (r < n_rows) ? x[r] : 0;
        toks[tid] = (tok & 1) ? tok : 0;   // even ids -> row 0
    }

    const uint32_t mbar0 = smem_u32(&mbar[0]);
    if (tid == 0) {
#pragma unroll
        for (int s = 0; s < STAGES; s++) mbar_init(mbar0 + s * 8, 1);
        asm volatile("fence.proxy.async.shared::cta;" ::: "memory");
    }
    __syncthreads();

    if (tid == 0) {
        const uint32_t buf0 = smem_u32(&buf[0][0]);
        const int rows = (n_rows - base < ROWS_PER_CTA) ? (n_rows - base)
                                                        : ROWS_PER_CTA;

        // Prologue: fill the pipeline DIST deep.
        int pro = (rows < DIST) ? rows : DIST;
        for (int j = 0; j < pro; j++) {
            mbar_expect_tx(mbar0 + j * 8, ROW_BYTES);
            bulk_load(buf0 + j * ROW_BYTES,
                      emb + (size_t)toks[j] * ROW_BYTES,
                      ROW_BYTES, mbar0 + j * 8);
        }

        for (int it = 0; it < rows; it++) {
            const int slot = it & (STAGES - 1);
            const uint32_t parity = (it >> 3) & 1;

            // Row `it` arrived?
            mbar_wait_parity(mbar0 + slot * 8, parity);

            // Ship it out.
            bulk_store(out + (size_t)(base + it) * ROW_BYTES,
                       buf0 + slot * ROW_BYTES, ROW_BYTES);
            bulk_commit();

            // Refill: row it+DIST into slot (it+DIST)%8 = (it-2)%8.
            // Its previous store committed at iteration it-2; wait_group.read 2
            // leaves at most stores {it-1, it} pending => store(it-2) has
            // finished reading smem, slot is safe to overwrite.
            const int j = it + DIST;
            if (j < rows) {
                bulk_wait_read<2>();
                const int rs = j & (STAGES - 1);
                mbar_expect_tx(mbar0 + rs * 8, ROW_BYTES);
                bulk_load(buf0 + rs * ROW_BYTES,
                          emb + (size_t)toks[j] * ROW_BYTES,
                          ROW_BYTES, mbar0 + rs * 8);
            }
        }

        // Drain all outstanding bulk stores before CTA exit.
        bulk_wait_all<0>();
    }
}

extern "C" void kernel_launch(void* const* d_in, const int* in_sizes, int n_in,
                              void* d_out, int out_size) {
    const int* x    = (const int*)d_in[0];
    const char* emb = (const char*)d_in[1];
    char* out       = (char*)d_out;

    int n_rows   = in_sizes[0];                                   // 32768
    int n_blocks = (n_rows + ROWS_PER_CTA - 1) / ROWS_PER_CTA;    // 1024

    embed_tma_kernel<<<n_blocks, THREADS>>>(x, emb, out, n_rows);
}

// round 5
// speedup vs baseline: 1.4886x; 1.4886x over previous
#include <cuda_runtime.h>
#include <cstdint>

// Embedding gather with even-token-id remap to 0.
// x: [32768] int32; emb: [50257, 512] f32; out: [32768, 512] f32.
// even ids -> id 0 (reference: jnp.where(x % 2 == 0, 0, x)).
//
// 256 threads/CTA, 16 rows/CTA, 8 float4 copies per thread.
// All 8 STG.128s live in ONE asm block (base reg + immediate offsets), so
// every LDG.128 result is live until the block: ptxas must front-batch all
// 8 loads -> true MLP=8 per thread.

static constexpr int VEC_PER_ROW   = 128;  // float4 per row
static constexpr int ROWS_PER_BLOCK = 16;
static constexpr int THREADS        = 256;

__global__ __launch_bounds__(THREADS)
void embed_gather_kernel(const int* __restrict__ x,
                         const float4* __restrict__ emb,
                         float4* __restrict__ out,
                         int n_rows) {
    __shared__ int toks[ROWS_PER_BLOCK];

    const int base = blockIdx.x * ROWS_PER_BLOCK;
    const int tid  = threadIdx.x;

    if (tid < ROWS_PER_BLOCK) {
        int r = base + tid;
        int tok = (r < n_rows) ? x[r] : 0;
        toks[tid] = (tok & 1) ? tok : 0;   // even ids -> row 0
    }
    __syncthreads();

    // chunk c covers rows {2c, 2c+1}; within a chunk, threads 0..127 read
    // row 2c, threads 128..255 read row 2c+1. col = tid & 127 (coalesced).
    const int rhi = tid >> 7;        // 0 or 1
    const int col = tid & 127;

    float4 v0 = __ldg(emb + (size_t)toks[ 0 + rhi] * VEC_PER_ROW + col);
    float4 v1 = __ldg(emb + (size_t)toks[ 2 + rhi] * VEC_PER_ROW + col);
    float4 v2 = __ldg(emb + (size_t)toks[ 4 + rhi] * VEC_PER_ROW + col);
    float4 v3 = __ldg(emb + (size_t)toks[ 6 + rhi] * VEC_PER_ROW + col);
    float4 v4 = __ldg(emb + (size_t)toks[ 8 + rhi] * VEC_PER_ROW + col);
    float4 v5 = __ldg(emb + (size_t)toks[10 + rhi] * VEC_PER_ROW + col);
    float4 v6 = __ldg(emb + (size_t)toks[12 + rhi] * VEC_PER_ROW + col);
    float4 v7 = __ldg(emb + (size_t)toks[14 + rhi] * VEC_PER_ROW + col);

    // dst element for chunk c is (c*256 + tid) float4s past out+base*128:
    // byte offset = c*4096 + tid*16.
    char* dbase = (char*)(out + (size_t)base * VEC_PER_ROW) + (size_t)tid * 16;

    asm volatile(
        "st.global.v4.f32 [%0+0],     {%1,  %2,  %3,  %4};\n\t"
        "st.global.v4.f32 [%0+4096],  {%5,  %6,  %7,  %8};\n\t"
        "st.global.v4.f32 [%0+8192],  {%9,  %10, %11, %12};\n\t"
        "st.global.v4.f32 [%0+12288], {%13, %14, %15, %16};\n\t"
        "st.global.v4.f32 [%0+16384], {%17, %18, %19, %20};\n\t"
        "st.global.v4.f32 [%0+20480], {%21, %22, %23, %24};\n\t"
        "st.global.v4.f32 [%0+24576], {%25, %26, %27, %28};\n\t"
        "st.global.v4.f32 [%0+28672], {%29, %30, %31, %32};\n\t"
        :
        : "l"(dbase),
          "f"(v0.x), "f"(v0.y), "f"(v0.z), "f"(v0.w),
          "f"(v1.x), "f"(v1.y), "f"(v1.z), "f"(v1.w),
          "f"(v2.x), "f"(v2.y), "f"(v2.z), "f"(v2.w),
          "f"(v3.x), "f"(v3.y), "f"(v3.z), "f"(v3.w),
          "f"(v4.x), "f"(v4.y), "f"(v4.z), "f"(v4.w),
          "f"(v5.x), "f"(v5.y), "f"(v5.z), "f"(v5.w),
          "f"(v6.x), "f"(v6.y), "f"(v6.z), "f"(v6.w),
          "f"(v7.x), "f"(v7.y), "f"(v7.z), "f"(v7.w)
        : "memory");
}

extern "C" void kernel_launch(void* const* d_in, const int* in_sizes, int n_in,
                              void* d_out, int out_size) {
    const int* x      = (const int*)d_in[0];
    const float4* emb = (const float4*)d_in[1];
    float4* out       = (float4*)d_out;

    int n_rows   = in_sizes[0];  // 32768
    int n_blocks = (n_rows + ROWS_PER_BLOCK - 1) / ROWS_PER_BLOCK;  // 2048

    embed_gather_kernel<<<n_blocks, THREADS>>>(x, emb, out, n_rows);
}